// round 11
// baseline (speedup 1.0000x reference)
#include <cuda_runtime.h>

#define NTOT 200      // histogram bins
#define TILEA 256     // A rows per block
#define TILEB 64      // B cols per block
#define BLKT 128      // threads per block (2 A rows per thread)
#define NWARP 4
#define NXB 64        // x buckets per band
#define NYB 4         // y bands
#define NBUCK (NXB * NYB)
#define GROUPS 16     // sorter blocks per array
#define BPB (NBUCK / GROUPS)
#define SORTT 512
#define SBATCH 8
#define MAXPTS 16384

// Sorted (y-band, then x) & prescaled points: (x,y,z)*real_size*20, w=|p|^2.
__device__ float4 g_pts[MAXPTS];
// 3 raw integer histograms: [0]=00-tri, [1]=01-cross, [2]=11-tri.
__device__ int g_hist[3 * NTOT];

__device__ __forceinline__ float fsqrt_approx(float x) {
    float r;
    asm("sqrt.approx.f32 %0, %1;" : "=f"(r) : "f"(x));
    return r;
}

__device__ __forceinline__ int bucket_of(float x, float y) {
    int xb = max(0, min(NXB - 1, (int)(x * (float)NXB)));
    int yb = max(0, min(NYB - 1, (int)(y * (float)NYB)));
    return yb * NXB + xb;
}

// Decentralized counting sort on (y-band, x) key. Every block counts the full
// histogram (batched loads, MLP=SBATCH), scans locally, scatters only its
// owned buckets. Within-bucket order is race-dependent -> fine (histogram is
// permutation-invariant).
__global__ __launch_bounds__(SORTT) void sort_kernel(
    const float* __restrict__ pos0, const float* __restrict__ pos1,
    const float* __restrict__ rs, int n0, int n1)
{
    __shared__ int cnt[NBUCK];
    __shared__ int cur[BPB];

    const int arr = blockIdx.x / GROUPS;
    const int grp = blockIdx.x - arr * GROUPS;
    const float* p = arr ? pos1 : pos0;
    const int n    = arr ? n1 : n0;
    const int base = arr ? n0 : 0;
    const int lo   = grp * BPB;
    const int tid  = threadIdx.x;

    const float r0 = rs[0] * 20.0f, r1 = rs[1] * 20.0f, r2 = rs[2] * 20.0f;

    for (int t = tid; t < NBUCK; t += SORTT) cnt[t] = 0;
    __syncthreads();

    // Pass 1: full bucket count, batched x,y loads.
    for (int b0 = 0; b0 < n; b0 += SORTT * SBATCH) {
        float xv[SBATCH], yv[SBATCH];
        bool  ok[SBATCH];
        #pragma unroll
        for (int k = 0; k < SBATCH; k++) {
            int i = b0 + tid + k * SORTT;
            ok[k] = (i < n);
            xv[k] = ok[k] ? p[3 * i + 0] : 0.0f;
            yv[k] = ok[k] ? p[3 * i + 1] : 0.0f;
        }
        #pragma unroll
        for (int k = 0; k < SBATCH; k++)
            if (ok[k]) atomicAdd(&cnt[bucket_of(xv[k], yv[k])], 1);
    }
    __syncthreads();

    // Exclusive scan via single-warp shuffle (lane L owns buckets [8L,8L+8)).
    if (tid < 32) {
        int v[8], s = 0;
        #pragma unroll
        for (int j = 0; j < 8; j++) { v[j] = cnt[tid * 8 + j]; s += v[j]; }
        int e = s;
        #pragma unroll
        for (int d = 1; d < 32; d <<= 1) {
            int t = __shfl_up_sync(0xFFFFFFFFu, e, d);
            if (tid >= d) e += t;
        }
        e -= s;
        #pragma unroll
        for (int j = 0; j < 8; j++) { int t = v[j]; cnt[tid * 8 + j] = e; e += t; }
    }
    __syncthreads();
    if (tid < BPB) cur[tid] = cnt[lo + tid];
    __syncthreads();

    // Pass 2: batched re-read (L2-hot); scatter owned points.
    for (int b0 = 0; b0 < n; b0 += SORTT * SBATCH) {
        float xv[SBATCH], yv[SBATCH];
        int   bk[SBATCH];
        #pragma unroll
        for (int k = 0; k < SBATCH; k++) {
            int i = b0 + tid + k * SORTT;
            bool ok = (i < n);
            xv[k] = ok ? p[3 * i + 0] : 0.0f;
            yv[k] = ok ? p[3 * i + 1] : 0.0f;
            bk[k] = ok ? 0 : -1;
        }
        #pragma unroll
        for (int k = 0; k < SBATCH; k++)
            if (bk[k] == 0) bk[k] = bucket_of(xv[k], yv[k]);
        #pragma unroll
        for (int k = 0; k < SBATCH; k++) {
            int b = bk[k];
            if (b >= lo && b < lo + BPB) {
                int i = b0 + tid + k * SORTT;
                float z = p[3 * i + 2];
                int pos = atomicAdd(&cur[b - lo], 1);
                float sx = xv[k] * r0, sy = yv[k] * r1, sz = z * r2;
                float q = sx * sx; q = fmaf(sy, sy, q); q = fmaf(sz, sz, q);
                g_pts[base + pos] = make_float4(sx, sy, sz, q);
            }
        }
    }
}

// Invert upper-triangle linear index t -> (bi, bj), bj >= bi.
__device__ __forceinline__ void tri_decode(int t, int n, int& bi, int& bj) {
    float fn = (float)(2 * n + 1);
    int b = (int)((fn - sqrtf(fmaxf(fn * fn - 8.0f * (float)t, 0.0f))) * 0.5f);
    if (b < 0) b = 0;
    if (b > n - 1) b = n - 1;
    while (b > 0 && t < b * (2 * n - b + 1) / 2) b--;
    while (b < n - 1 && t >= (b + 1) * (2 * n - b) / 2) b++;
    bi = b;
    bj = b + (t - b * (2 * n - b + 1) / 2);
}

// All three pair regions in one grid; 256x64 work blocks (2 waves / SM).
// 2D bbox cull: exact A/B bounding boxes reduced in-block; skip the inner
// loop when the box-gap lower bound exceeds the cutoff.
__global__ __launch_bounds__(BLKT, 16) void pair_fused_kernel(
    int n0, int n1, int nb0, int nb1, int T0, int C)
{
    __shared__ float4 sB[TILEB];
    __shared__ int    sh[NWARP * NTOT];
    __shared__ float  red[NWARP][8];
    __shared__ int    s_cull;

    int w    = blockIdx.x >> 2;
    int quar = blockIdx.x & 3;
    int bi, bj, aOff, bOff, nA, nB, histIdx;
    bool diag;
    if (w < T0) {                     // 0-0 triangle
        tri_decode(w, nb0, bi, bj);
        aOff = 0; bOff = 0; nA = n0; nB = n0; histIdx = 0;
        diag = (bi == bj);
    } else if (w < T0 + C) {          // 0-1 cross
        int u = w - T0;
        bi = u / nb1; bj = u - bi * nb1;
        aOff = 0; nA = n0; bOff = n0; nB = n1; histIdx = 1;
        diag = false;
    } else {                          // 1-1 triangle
        int u = w - T0 - C;
        tri_decode(u, nb1, bi, bj);
        aOff = n0; bOff = n0; nA = n1; nB = n1; histIdx = 2;
        diag = (bi == bj);
    }
    const int rowStart  = bi * TILEA;
    const int chunkBase = bj * TILEA + quar * TILEB;
    if (chunkBase >= nB) return;

    const int tid  = threadIdx.x;
    const int wid  = tid >> 5;
    const int lane = tid & 31;

    // ---- load B chunk (own element only -> no sync needed yet) ----
    float4 myB = make_float4(0.f, 0.f, 0.f, 1e30f);
    if (tid < TILEB) {
        int j = chunkBase + tid;
        if (j < nB) myB = g_pts[bOff + j];
        sB[tid] = myB;
    }

    // ---- load A rows ----
    float ax[2], ay[2], az[2], aw[2];
    int   irow[2];
    #pragma unroll
    for (int t = 0; t < 2; t++) {
        int i = rowStart + tid + t * BLKT;
        irow[t] = i;
        float4 a = (i < nA) ? g_pts[aOff + i]
                            : make_float4(0.f, 0.f, 0.f, 1e30f);
        ax[t] = a.x; ay[t] = a.y; az[t] = a.z; aw[t] = a.w;
    }

    // ---- bbox reduction (A and B separately; invalid pts have w=1e30) ----
    float axmn = 1e30f, axmx = -1e30f, aymn = 1e30f, aymx = -1e30f;
    #pragma unroll
    for (int t = 0; t < 2; t++) {
        if (aw[t] < 1e29f) {
            axmn = fminf(axmn, ax[t]); axmx = fmaxf(axmx, ax[t]);
            aymn = fminf(aymn, ay[t]); aymx = fmaxf(aymx, ay[t]);
        }
    }
    float bxmn = 1e30f, bxmx = -1e30f, bymn = 1e30f, bymx = -1e30f;
    if (tid < TILEB && myB.w < 1e29f) {
        bxmn = myB.x; bxmx = myB.x; bymn = myB.y; bymx = myB.y;
    }
    #pragma unroll
    for (int d = 16; d >= 1; d >>= 1) {
        axmn = fminf(axmn, __shfl_xor_sync(0xFFFFFFFFu, axmn, d));
        axmx = fmaxf(axmx, __shfl_xor_sync(0xFFFFFFFFu, axmx, d));
        aymn = fminf(aymn, __shfl_xor_sync(0xFFFFFFFFu, aymn, d));
        aymx = fmaxf(aymx, __shfl_xor_sync(0xFFFFFFFFu, aymx, d));
        bxmn = fminf(bxmn, __shfl_xor_sync(0xFFFFFFFFu, bxmn, d));
        bxmx = fmaxf(bxmx, __shfl_xor_sync(0xFFFFFFFFu, bxmx, d));
        bymn = fminf(bymn, __shfl_xor_sync(0xFFFFFFFFu, bymn, d));
        bymx = fmaxf(bymx, __shfl_xor_sync(0xFFFFFFFFu, bymx, d));
    }
    if (lane == 0) {
        red[wid][0] = axmn; red[wid][1] = axmx;
        red[wid][2] = aymn; red[wid][3] = aymx;
        red[wid][4] = bxmn; red[wid][5] = bxmx;
        red[wid][6] = bymn; red[wid][7] = bymx;
    }
    __syncthreads();
    if (tid == 0) {
        float v0 = red[0][0], v1 = red[0][1], v2 = red[0][2], v3 = red[0][3];
        float v4 = red[0][4], v5 = red[0][5], v6 = red[0][6], v7 = red[0][7];
        #pragma unroll
        for (int q = 1; q < NWARP; q++) {
            v0 = fminf(v0, red[q][0]); v1 = fmaxf(v1, red[q][1]);
            v2 = fminf(v2, red[q][2]); v3 = fmaxf(v3, red[q][3]);
            v4 = fminf(v4, red[q][4]); v5 = fmaxf(v5, red[q][5]);
            v6 = fminf(v6, red[q][6]); v7 = fmaxf(v7, red[q][7]);
        }
        float gx = fmaxf(0.0f, fmaxf(v4 - v1, v0 - v5));
        float gy = fmaxf(0.0f, fmaxf(v6 - v3, v2 - v7));
        // cull iff the box-gap lower bound on d^2 exceeds (200.2)^2:
        // every culled pair has bin >= 200 -> dropped by reference too.
        s_cull = (fmaf(gx, gx, gy * gy) > 40080.0f) ? 1 : 0;
    }
    __syncthreads();
    if (s_cull) return;

    int* myh = &sh[wid * NTOT];
    #pragma unroll
    for (int idx = tid; idx < NWARP * NTOT; idx += BLKT) sh[idx] = 0;

    float ax2[2], ay2[2], az2[2];
    #pragma unroll
    for (int t = 0; t < 2; t++) {
        ax2[t] = -2.0f * ax[t]; ay2[t] = -2.0f * ay[t]; az2[t] = -2.0f * az[t];
    }
    __syncthreads();

    if (diag) {
        #pragma unroll 4
        for (int k = 0; k < TILEB; k++) {
            float4 b = sB[k];
            float s0 = aw[0] + b.w;
            s0 = fmaf(ax2[0], b.x, s0);
            s0 = fmaf(ay2[0], b.y, s0);
            s0 = fmaf(az2[0], b.z, s0);
            float s1 = aw[1] + b.w;
            s1 = fmaf(ax2[1], b.x, s1);
            s1 = fmaf(ay2[1], b.y, s1);
            s1 = fmaf(az2[1], b.z, s1);
            if (__ballot_sync(0xFFFFFFFFu, fminf(s0, s1) < 40000.0f) == 0u)
                continue;
            float d0 = fsqrt_approx(fmaxf(s0, 0.0f));
            if (d0 < (float)NTOT && (chunkBase + k) > irow[0])
                atomicAdd(&myh[(int)d0], 1);
            float d1 = fsqrt_approx(fmaxf(s1, 0.0f));
            if (d1 < (float)NTOT && (chunkBase + k) > irow[1])
                atomicAdd(&myh[(int)d1], 1);
        }
    } else {
        #pragma unroll 4
        for (int k = 0; k < TILEB; k++) {
            float4 b = sB[k];
            float s0 = aw[0] + b.w;
            s0 = fmaf(ax2[0], b.x, s0);
            s0 = fmaf(ay2[0], b.y, s0);
            s0 = fmaf(az2[0], b.z, s0);
            float s1 = aw[1] + b.w;
            s1 = fmaf(ax2[1], b.x, s1);
            s1 = fmaf(ay2[1], b.y, s1);
            s1 = fmaf(az2[1], b.z, s1);
            if (__ballot_sync(0xFFFFFFFFu, fminf(s0, s1) < 40000.0f) == 0u)
                continue;
            float d0 = fsqrt_approx(fmaxf(s0, 0.0f));
            if (d0 < (float)NTOT) atomicAdd(&myh[(int)d0], 1);
            float d1 = fsqrt_approx(fmaxf(s1, 0.0f));
            if (d1 < (float)NTOT) atomicAdd(&myh[(int)d1], 1);
        }
    }
    __syncthreads();

    for (int t = tid; t < NTOT; t += BLKT) {
        int v = sh[t] + sh[NTOT + t] + sh[2 * NTOT + t] + sh[3 * NTOT + t];
        if (v) atomicAdd(&g_hist[histIdx * NTOT + t], v);
    }
}

// Single block: normalize all 800 outputs, then zero g_hist for next replay.
__global__ void finalize_kernel(const float* __restrict__ count_in,
                                float* __restrict__ out,
                                const float* __restrict__ rs,
                                int n0, int n1)
{
    int idx = threadIdx.x;
    if (idx < 4 * NTOT) {
        int k  = idx % NTOT;
        int ij = idx / NTOT;
        int histIdx = (ij == 0) ? 0 : ((ij == 3) ? 2 : 1);
        float mult  = (ij == 0 || ij == 3) ? 2.0f : 1.0f;
        float na = (float)((ij >> 1) ? n1 : n0);
        float nb = (float)((ij & 1) ? n1 : n0);
        float vol = rs[0] * rs[1] * rs[2];

        float counts = (float)g_hist[histIdx * NTOT + k] * mult;
        double r = 0.025 + (double)k * 0.05;
        float sv = (float)(r * 0.05 * 2.0 * 3.14159265358979323846 * 3.0);
        float density = nb / vol;
        float res = counts / density / sv / na;
        out[idx] = count_in[idx] + res;
    }
    __syncthreads();
    if (idx < 3 * NTOT) g_hist[idx] = 0;
}

extern "C" void kernel_launch(void* const* d_in, const int* in_sizes, int n_in,
                              void* d_out, int out_size)
{
    const float* pos0  = (const float*)d_in[0];
    const float* pos1  = (const float*)d_in[1];
    const float* count = (const float*)d_in[2];
    const float* rs    = (const float*)d_in[3];
    int n0 = in_sizes[0] / 3;
    int n1 = in_sizes[1] / 3;
    float* out = (float*)d_out;

    sort_kernel<<<2 * GROUPS, SORTT>>>(pos0, pos1, rs, n0, n1);

    int nb0 = (n0 + TILEA - 1) / TILEA;
    int nb1 = (n1 + TILEA - 1) / TILEA;
    int T0 = nb0 * (nb0 + 1) / 2;
    int C  = nb0 * nb1;
    int T1 = nb1 * (nb1 + 1) / 2;
    pair_fused_kernel<<<4 * (T0 + C + T1), BLKT>>>(n0, n1, nb0, nb1, T0, C);

    finalize_kernel<<<1, 4 * NTOT>>>(count, out, rs, n0, n1);
}